// round 3
// baseline (speedup 1.0000x reference)
#include <cuda_runtime.h>
#include <math.h>

#define N_NODES 50000
#define N_EDGES 800000
#define F_DIM   128
#define F4      32      // float4 per feature row
#define HID     256
#define NCLS    40

#define SCAN_BLOCKS ((N_NODES + 255) / 256)   // 196

// ---------------- device scratch (static: no allocation allowed) ----------------
__device__ int    g_deg[N_NODES];
__device__ int    g_rowstart[N_NODES + 1];
__device__ int    g_cursor[N_NODES];
__device__ int    g_bsum[SCAN_BLOCKS];
__device__ int    g_boff[SCAN_BLOCKS];
__device__ float  g_norm[N_NODES];
__device__ int2   g_csr[N_EDGES];           // (src, norm[src] as bits)
__device__ float4 g_x1[N_NODES * F4];
__device__ float4 g_x2[N_NODES * F4];
__device__ float4 g_y [N_NODES * F4];
__device__ float4 g_h [N_NODES * (HID / 4)];

// ---------------- f32x2 packed helpers (Blackwell dual-lane fp32) ----------------
__device__ __forceinline__ unsigned long long pack2(float lo, float hi) {
    unsigned long long r;
    asm("mov.b64 %0, {%1, %2};" : "=l"(r) : "f"(lo), "f"(hi));
    return r;
}
__device__ __forceinline__ void unpack2(unsigned long long v, float& lo, float& hi) {
    asm("mov.b64 {%0, %1}, %2;" : "=f"(lo), "=f"(hi) : "l"(v));
}
__device__ __forceinline__ unsigned long long fma2(unsigned long long a,
                                                   unsigned long long b,
                                                   unsigned long long c) {
    unsigned long long d;
    asm("fma.rn.f32x2 %0, %1, %2, %3;" : "=l"(d) : "l"(a), "l"(b), "l"(c));
    return d;
}

// ---------------- build: degree ----------------
__global__ void zero_deg_kernel() {
    int i = blockIdx.x * blockDim.x + threadIdx.x;
    if (i < N_NODES) g_deg[i] = 0;
}

__global__ void deg_kernel(const int* __restrict__ dst) {
    int i = blockIdx.x * blockDim.x + threadIdx.x;
    if (i < N_EDGES) atomicAdd(&g_deg[dst[i]], 1);
}

__global__ void norm_kernel() {
    int i = blockIdx.x * blockDim.x + threadIdx.x;
    if (i < N_NODES) {
        int d = g_deg[i];
        g_norm[i] = rsqrtf((float)(d < 1 ? 1 : d));
    }
}

// ---------------- hierarchical scan ----------------
__device__ __forceinline__ int warp_incl_scan(int v, int lane) {
#pragma unroll
    for (int o = 1; o < 32; o <<= 1) {
        int n = __shfl_up_sync(0xffffffffu, v, o);
        if (lane >= o) v += n;
    }
    return v;
}

__device__ __forceinline__ int block_incl_scan_256(int v, int tid) {
    __shared__ int ws[8];
    int lane = tid & 31, w = tid >> 5;
    int incl = warp_incl_scan(v, lane);
    if (lane == 31) ws[w] = incl;
    __syncthreads();
    if (w == 0) {
        int s = (lane < 8) ? ws[lane] : 0;
        s = warp_incl_scan(s, lane);
        if (lane < 8) ws[lane] = s;
    }
    __syncthreads();
    if (w > 0) incl += ws[w - 1];
    return incl;
}

__global__ void scan1_kernel() {
    int tid = threadIdx.x;
    int i = blockIdx.x * 256 + tid;
    int v = (i < N_NODES) ? g_deg[i] : 0;
    int incl = block_incl_scan_256(v, tid);
    if (i < N_NODES) g_rowstart[i] = incl - v;
    if (tid == 255) g_bsum[blockIdx.x] = incl;
}

__global__ void scan2_kernel() {
    int tid = threadIdx.x;
    int v = (tid < SCAN_BLOCKS) ? g_bsum[tid] : 0;
    int incl = block_incl_scan_256(v, tid);
    if (tid < SCAN_BLOCKS) g_boff[tid] = incl - v;
}

__global__ void scan3_kernel() {
    int i = blockIdx.x * 256 + threadIdx.x;
    if (i < N_NODES) {
        int r = g_rowstart[i] + g_boff[blockIdx.x];
        g_rowstart[i] = r;
        g_cursor[i]   = r;
    }
    if (i == 0) g_rowstart[N_NODES] = N_EDGES;
}

// fill CSR: (src, norm[src]) interleaved
__global__ void fill_kernel(const int* __restrict__ src, const int* __restrict__ dst) {
    int i = blockIdx.x * blockDim.x + threadIdx.x;
    if (i < N_EDGES) {
        int s = src[i];
        int d = dst[i];
        int pos = atomicAdd(&g_cursor[d], 1);
        int2 v;
        v.x = s;
        v.y = __float_as_int(g_norm[s]);
        g_csr[pos] = v;
    }
}

// ---------------- propagation: pull over CSR, fused y-accumulate ----------------
// block = 256 threads = 8 nodes x 32 lanes; lane owns 4 feature dims (float4)
// FIRST step: xin = features; y = feat[node] + norm*acc (replaces init kernel)
template<bool FIRST>
__global__ void prop_kernel(const float4* __restrict__ xin, float4* __restrict__ xout) {
    int node = blockIdx.x * 8 + (threadIdx.x >> 5);
    int lane = threadIdx.x & 31;
    if (node >= N_NODES) return;

    int beg = g_rowstart[node];
    int end = g_rowstart[node + 1];

    float4 acc = make_float4(0.f, 0.f, 0.f, 0.f);
    int e = beg;
    for (; e + 4 <= end; e += 4) {
        int2 c0 = __ldg(&g_csr[e + 0]);
        int2 c1 = __ldg(&g_csr[e + 1]);
        int2 c2 = __ldg(&g_csr[e + 2]);
        int2 c3 = __ldg(&g_csr[e + 3]);
        float4 v0 = __ldg(&xin[c0.x * F4 + lane]);
        float4 v1 = __ldg(&xin[c1.x * F4 + lane]);
        float4 v2 = __ldg(&xin[c2.x * F4 + lane]);
        float4 v3 = __ldg(&xin[c3.x * F4 + lane]);
        float w0 = __int_as_float(c0.y);
        float w1 = __int_as_float(c1.y);
        float w2 = __int_as_float(c2.y);
        float w3 = __int_as_float(c3.y);
        acc.x = fmaf(v0.x, w0, acc.x); acc.y = fmaf(v0.y, w0, acc.y);
        acc.z = fmaf(v0.z, w0, acc.z); acc.w = fmaf(v0.w, w0, acc.w);
        acc.x = fmaf(v1.x, w1, acc.x); acc.y = fmaf(v1.y, w1, acc.y);
        acc.z = fmaf(v1.z, w1, acc.z); acc.w = fmaf(v1.w, w1, acc.w);
        acc.x = fmaf(v2.x, w2, acc.x); acc.y = fmaf(v2.y, w2, acc.y);
        acc.z = fmaf(v2.z, w2, acc.z); acc.w = fmaf(v2.w, w2, acc.w);
        acc.x = fmaf(v3.x, w3, acc.x); acc.y = fmaf(v3.y, w3, acc.y);
        acc.z = fmaf(v3.z, w3, acc.z); acc.w = fmaf(v3.w, w3, acc.w);
    }
    for (; e < end; e++) {
        int2 c = __ldg(&g_csr[e]);
        float w = __int_as_float(c.y);
        float4 v = __ldg(&xin[c.x * F4 + lane]);
        acc.x = fmaf(v.x, w, acc.x); acc.y = fmaf(v.y, w, acc.y);
        acc.z = fmaf(v.z, w, acc.z); acc.w = fmaf(v.w, w, acc.w);
    }

    float nd = g_norm[node];
    acc.x *= nd; acc.y *= nd; acc.z *= nd; acc.w *= nd;

    int idx = node * F4 + lane;
    xout[idx] = acc;
    float4 yv;
    if (FIRST) {
        yv = __ldg(&xin[idx]);       // features[node], same array being gathered
    } else {
        yv = g_y[idx];
    }
    yv.x += acc.x; yv.y += acc.y; yv.z += acc.z; yv.w += acc.w;
    g_y[idx] = yv;
}

// ---------------- GEMM1: h = relu( (y*0.25) @ W1 + b1 )  [50000,128]x[128,256] ----
// BM=128, BN=64, BK=16, 256 threads, 8x4 per thread, f32x2 packed inner loop
__global__ void gemm1_kernel(const float* __restrict__ W1, const float* __restrict__ b1) {
    __shared__ __align__(16) float As[16][132];   // [k][m], padded
    __shared__ __align__(16) float Bs[16][64];    // [k][n]

    int tid = threadIdx.x;
    int m0 = blockIdx.x * 128;
    int n0 = blockIdx.y * 64;
    int ty = tid >> 4;          // 0..15 -> 8 rows each
    int tx = tid & 15;          // 0..15 -> 4 cols each

    const float* y = (const float*)g_y;

    int arow = tid >> 1;            // 0..127
    int ak   = (tid & 1) * 8;       // 0 or 8
    int brow = tid >> 4;            // 0..15
    int bc   = (tid & 15) * 4;      // 0..60

    // acc2[p][j] packs output rows (2p, 2p+1) for column j
    unsigned long long acc2[4][4];
#pragma unroll
    for (int p = 0; p < 4; p++)
#pragma unroll
        for (int j = 0; j < 4; j++) acc2[p][j] = 0ull;

    for (int k0 = 0; k0 < F_DIM; k0 += 16) {
        int gm = m0 + arow;
        float4 av0 = make_float4(0.f, 0.f, 0.f, 0.f);
        float4 av1 = make_float4(0.f, 0.f, 0.f, 0.f);
        if (gm < N_NODES) {
            av0 = *(const float4*)&y[gm * F_DIM + k0 + ak];
            av1 = *(const float4*)&y[gm * F_DIM + k0 + ak + 4];
        }
        As[ak + 0][arow] = av0.x * 0.25f;
        As[ak + 1][arow] = av0.y * 0.25f;
        As[ak + 2][arow] = av0.z * 0.25f;
        As[ak + 3][arow] = av0.w * 0.25f;
        As[ak + 4][arow] = av1.x * 0.25f;
        As[ak + 5][arow] = av1.y * 0.25f;
        As[ak + 6][arow] = av1.z * 0.25f;
        As[ak + 7][arow] = av1.w * 0.25f;

        float4 bv = *(const float4*)&W1[(k0 + brow) * HID + n0 + bc];
        *(float4*)&Bs[brow][bc] = bv;

        __syncthreads();
#pragma unroll
        for (int kk = 0; kk < 16; kk++) {
            // A pairs load directly as packed 64-bit lanes (rows 2p,2p+1)
            ulonglong2 a01 = *(const ulonglong2*)&As[kk][ty * 8];
            ulonglong2 a23 = *(const ulonglong2*)&As[kk][ty * 8 + 4];
            float4 b4 = *(const float4*)&Bs[kk][tx * 4];
            unsigned long long bb[4];
            bb[0] = pack2(b4.x, b4.x);
            bb[1] = pack2(b4.y, b4.y);
            bb[2] = pack2(b4.z, b4.z);
            bb[3] = pack2(b4.w, b4.w);
#pragma unroll
            for (int j = 0; j < 4; j++) {
                acc2[0][j] = fma2(a01.x, bb[j], acc2[0][j]);
                acc2[1][j] = fma2(a01.y, bb[j], acc2[1][j]);
                acc2[2][j] = fma2(a23.x, bb[j], acc2[2][j]);
                acc2[3][j] = fma2(a23.y, bb[j], acc2[3][j]);
            }
        }
        __syncthreads();
    }

    float4 bias = *(const float4*)&b1[n0 + tx * 4];
    float* h = (float*)g_h;
#pragma unroll
    for (int p = 0; p < 4; p++) {
        float lo[4], hi[4];
#pragma unroll
        for (int j = 0; j < 4; j++) unpack2(acc2[p][j], lo[j], hi[j]);
        int gm0 = m0 + ty * 8 + 2 * p;
        if (gm0 < N_NODES) {
            float4 o;
            o.x = fmaxf(lo[0] + bias.x, 0.f);
            o.y = fmaxf(lo[1] + bias.y, 0.f);
            o.z = fmaxf(lo[2] + bias.z, 0.f);
            o.w = fmaxf(lo[3] + bias.w, 0.f);
            *(float4*)&h[gm0 * HID + n0 + tx * 4] = o;
        }
        if (gm0 + 1 < N_NODES) {
            float4 o;
            o.x = fmaxf(hi[0] + bias.x, 0.f);
            o.y = fmaxf(hi[1] + bias.y, 0.f);
            o.z = fmaxf(hi[2] + bias.z, 0.f);
            o.w = fmaxf(hi[3] + bias.w, 0.f);
            *(float4*)&h[(gm0 + 1) * HID + n0 + tx * 4] = o;
        }
    }
}

// ---------------- GEMM2 + log_softmax fused: out = logsoftmax(h @ W2 + b2) -------
__global__ void gemm2_kernel(const float* __restrict__ W2, const float* __restrict__ b2,
                             float* __restrict__ out) {
    __shared__ __align__(16) float w2c[32][44];
    __shared__ __align__(16) float hc[32][33];
    __shared__ float lg[32][41];
    __shared__ float rm[32], rs[32];

    int tid = threadIdx.x;          // 0..319
    int r = tid / 10;               // 0..31
    int g = tid % 10;               // 0..9  -> classes 4g..4g+3
    int m0 = blockIdx.x * 32;

    const float* h = (const float*)g_h;

    unsigned long long p01 = 0ull, p23 = 0ull;

    for (int kb = 0; kb < HID; kb += 32) {
        for (int idx = tid; idx < 32 * 32; idx += 320) {
            int rr = idx >> 5, kk = idx & 31;
            int row = m0 + rr;
            hc[rr][kk] = (row < N_NODES) ? h[row * HID + kb + kk] : 0.f;
        }
        for (int idx = tid; idx < 32 * 40; idx += 320) {
            int kk = idx / 40, cc = idx % 40;
            w2c[kk][cc] = W2[(kb + kk) * NCLS + cc];
        }
        __syncthreads();
#pragma unroll
        for (int kk = 0; kk < 32; kk++) {
            float hv = hc[r][kk];
            unsigned long long hh = pack2(hv, hv);
            ulonglong2 wp = *(const ulonglong2*)&w2c[kk][g * 4];
            p01 = fma2(hh, wp.x, p01);
            p23 = fma2(hh, wp.y, p23);
        }
        __syncthreads();
    }

    float a0, a1, a2, a3;
    unpack2(p01, a0, a1);
    unpack2(p23, a2, a3);

    lg[r][g * 4 + 0] = a0 + b2[g * 4 + 0];
    lg[r][g * 4 + 1] = a1 + b2[g * 4 + 1];
    lg[r][g * 4 + 2] = a2 + b2[g * 4 + 2];
    lg[r][g * 4 + 3] = a3 + b2[g * 4 + 3];
    __syncthreads();

    if (tid < 32) {
        float m = -1e30f;
#pragma unroll
        for (int c = 0; c < NCLS; c++) m = fmaxf(m, lg[tid][c]);
        float s = 0.f;
#pragma unroll
        for (int c = 0; c < NCLS; c++) s += expf(lg[tid][c] - m);
        rm[tid] = m;
        rs[tid] = logf(s);
    }
    __syncthreads();

    int row = m0 + r;
    if (row < N_NODES) {
        float sub = rm[r] + rs[r];
        out[row * NCLS + g * 4 + 0] = lg[r][g * 4 + 0] - sub;
        out[row * NCLS + g * 4 + 1] = lg[r][g * 4 + 1] - sub;
        out[row * NCLS + g * 4 + 2] = lg[r][g * 4 + 2] - sub;
        out[row * NCLS + g * 4 + 3] = lg[r][g * 4 + 3] - sub;
    }
}

// ---------------- launch ----------------
extern "C" void kernel_launch(void* const* d_in, const int* in_sizes, int n_in,
                              void* d_out, int out_size) {
    const float* features = (const float*)d_in[0];
    const int*   src      = (const int*)d_in[1];
    const int*   dst      = (const int*)d_in[2];
    const float* W1       = (const float*)d_in[3];
    const float* b1       = (const float*)d_in[4];
    const float* W2       = (const float*)d_in[5];
    const float* b2       = (const float*)d_in[6];
    float*       out      = (float*)d_out;

    const int NB  = (N_NODES + 255) / 256;      // 196
    const int EB  = (N_EDGES + 255) / 256;      // 3125
    const int PB  = (N_NODES + 7) / 8;          // 6250

    zero_deg_kernel<<<NB, 256>>>();
    deg_kernel<<<EB, 256>>>(dst);
    norm_kernel<<<NB, 256>>>();
    scan1_kernel<<<SCAN_BLOCKS, 256>>>();
    scan2_kernel<<<1, 256>>>();
    scan3_kernel<<<SCAN_BLOCKS, 256>>>();
    fill_kernel<<<EB, 256>>>(src, dst);

    prop_kernel<true ><<<PB, 256>>>((const float4*)features, g_x1);  // feat -> x1, y=feat+x1
    prop_kernel<false><<<PB, 256>>>(g_x1, g_x2);                     // x1 -> x2, y+=x2
    prop_kernel<false><<<PB, 256>>>(g_x2, g_x1);                     // x2 -> x3, y+=x3

    dim3 g1((N_NODES + 127) / 128, HID / 64);   // (391, 4)
    gemm1_kernel<<<g1, 256>>>(W1, b1);

    const int G2B = (N_NODES + 31) / 32;        // 1563
    gemm2_kernel<<<G2B, 320>>>(W2, b2, out);
}